// round 11
// baseline (speedup 1.0000x reference)
#include <cuda_runtime.h>

#define HH 1024
#define WW 1024
#define MM 512            // 16 segments * 32 samples
#define TW 16.0f          // sigmoid half-window; tail err ~1.1e-7
#define KCAP 192          // max active edges per block (2 rows, observed ~52)
#define BCAP 64           // max edges per 128-px bucket per row
#define NT 256
#define RPB 2             // rows per block

__global__ __launch_bounds__(NT)
void bvr_fused_kernel(const float* __restrict__ cp,
                      const float* __restrict__ color,
                      float* __restrict__ out)
{
    __shared__ float2 s_pts[MM];            // sampled path points
    __shared__ float  s_acc[RPB * WW];      // windowed contributions, row-tagged
    __shared__ float4 s_wk[KCAP];           // {w, f=exp(xlo-xc), xdst, xlim}
    __shared__ float2 s_bk[RPB * 9][BCAP];  // bucket lists: {w, xlo}
    __shared__ int    s_bcnt[RPB * 9];
    __shared__ float  s_btot[RPB * 9];
    __shared__ int    s_cnt;

    const int tid  = threadIdx.x;
    const int lane = tid & 31;
    const int y0   = blockIdx.x * RPB;
    const float fy0 = (float)y0;
    const float elane = __expf((float)lane);

    if (tid < RPB * 9) { s_bcnt[tid] = 0; s_btot[tid] = 0.0f; }
    if (tid == 0) s_cnt = 0;
    #pragma unroll
    for (int it = 0; it < RPB * WW / NT; ++it) s_acc[tid + it * NT] = 0.0f;

    // ---- 1. Sample Bezier path (2 points per thread) ----
    #pragma unroll
    for (int it = 0; it < 2; ++it) {
        int i = tid + it * NT;
        int s = i >> 5;
        int j = i & 31;
        float t  = (float)j / 31.0f;
        float mt = 1.0f - t;
        float b0 = mt * mt * mt;
        float b1 = 3.0f * mt * mt * t;
        float b2 = 3.0f * mt * t * t;
        float b3 = t * t * t;
        const float* p = cp + 6 * s;
        float px = b0 * p[0] + b1 * p[2] + b2 * p[4] + b3 * p[6];
        float py = b0 * p[1] + b1 * p[3] + b2 * p[5] + b3 * p[7];
        s_pts[i] = make_float2(px, py);
    }
    __syncthreads();

    // ---- 2. Compact active edges (both rows) into window list + buckets ----
    #pragma unroll
    for (int it = 0; it < 2; ++it) {
        int e = tid + it * NT;
        float2 p0 = s_pts[e];
        float2 p1 = s_pts[(e + 1) & (MM - 1)];
        float dy = p1.y - p0.y;
        if (fabsf(dy) < 1e-6f) continue;            // coeff == 0 in reference

        float ba = p0.y - 1.2f * dy;                // |w|>1e-10 needs t in [-1.2,2.2]
        float bb = p0.y + 2.2f * dy;
        float lo = fminf(ba, bb), hi = fmaxf(ba, bb);
        if ((fy0 < lo || fy0 > hi) &&
            (fy0 + (RPB - 1) < lo || fy0 + (RPB - 1) > hi)) continue;

        float rinv  = __fdividef(1.0f, dy + 1e-8f);
        float coeff = (dy > 0.0f) ? 1.0f : -1.0f;
        float dx    = p1.x - p0.x;

        #pragma unroll
        for (int r = 0; r < RPB; ++r) {
            float fy = fy0 + (float)r;
            float t  = (fy - p0.y) * rinv;
            float v1 = 1.0f / (1.0f + __expf(-20.0f * t));
            float v2 = 1.0f / (1.0f + __expf(20.0f * (t - 1.0f)));
            float w  = coeff * v1 * v2;
            float xc = p0.x + t * dx;
            if (fabsf(w) < 1e-10f || xc < -TW) continue;

            int xlo = (int)ceilf(xc - TW);
            xlo = max(0, min(xlo, WW));
            float f = __expf((float)xlo - xc);

            int k = atomicAdd(&s_cnt, 1);
            s_wk[k] = make_float4(w, f, (float)(xlo + r * WW),
                                  (float)(r * WW + WW));

            int bkt  = r * 9 + (xlo >> 7);          // 8 bands + full-row bucket
            int slot = atomicAdd(&s_bcnt[bkt], 1);
            s_bk[bkt][slot] = make_float2(w, (float)xlo);
            atomicAdd(&s_btot[bkt], w);
        }
    }
    __syncthreads();

    const int Kt = s_cnt;

    // ---- 3a. Window scatter: warp-per-edge, lane = px offset ----
    for (int i = tid; i < (Kt << 5); i += NT) {
        int k = i >> 5;                             // warp-uniform
        float4 wk = s_wk[k];                        // broadcast LDS.128
        int x = (int)wk.z + lane;
        if ((float)x < wk.w) {
            float val = __fdividef(wk.x, fmaf(elane, wk.y, 1.0f));
            atomicAdd(&s_acc[x], val);
        }
    }

    // ---- 3b. Base per row: suffix buckets + own-bucket per-pixel step ----
    const int wrp = tid >> 5;                       // warp covers px [wrp*128,+128)
    const float bf = (float)(tid * 4);
    float wbase[RPB];
    float wa[RPB][4];

    #pragma unroll
    for (int r = 0; r < RPB; ++r) {
        float wb = 0.0f;
        #pragma unroll
        for (int j = 1; j <= 8; ++j)
            wb += (j > wrp) ? s_btot[r * 9 + j] : 0.0f;
        wbase[r] = wb;

        float a0 = 0.f, a1 = 0.f, a2 = 0.f, a3 = 0.f;
        const int cnt_own = s_bcnt[r * 9 + wrp];    // warp-uniform
        for (int s = 0; s < cnt_own; ++s) {
            float2 ek = s_bk[r * 9 + wrp][s];       // broadcast LDS.64
            float m = ek.y - bf;
            a0 += (0.0f < m) ? ek.x : 0.0f;
            a1 += (1.0f < m) ? ek.x : 0.0f;
            a2 += (2.0f < m) ? ek.x : 0.0f;
            a3 += (3.0f < m) ? ek.x : 0.0f;
        }
        wa[r][0] = a0; wa[r][1] = a1; wa[r][2] = a2; wa[r][3] = a3;
    }
    __syncthreads();

    // ---- 4. Alpha via tanh.approx + output (both rows) ----
    const float cr = __ldg(color + 0);
    const float cg = __ldg(color + 1);
    const float cb = __ldg(color + 2);
    const int b = tid * 4;

    #pragma unroll
    for (int r = 0; r < RPB; ++r) {
        float4* orow = (float4*)out + (size_t)(y0 + r) * WW + b;
        #pragma unroll
        for (int q = 0; q < 4; ++q) {
            float wind = wbase[r] + wa[r][q] + s_acc[r * WW + b + q];
            float th;
            asm("tanh.approx.f32 %0, %1;" : "=f"(th) : "f"(2.0f * wind));
            float a = fmaf(0.5f, th, 0.5f);
            orow[q] = make_float4(cr, cg, cb, a);
        }
    }
}

extern "C" void kernel_launch(void* const* d_in, const int* in_sizes, int n_in,
                              void* d_out, int out_size)
{
    const float* cp    = (const float*)d_in[0];   // (49, 2) float32
    const float* color = (const float*)d_in[1];   // (3,)   float32
    float* out = (float*)d_out;                   // (1024, 1024, 4) float32
    (void)in_sizes; (void)n_in; (void)out_size;
    bvr_fused_kernel<<<HH / RPB, NT>>>(cp, color, out);
}

// round 12
// speedup vs baseline: 1.3860x; 1.3860x over previous
#include <cuda_runtime.h>

#define HH 1024
#define WW 1024
#define MM 512            // 16 segments * 32 samples
#define TW 16.0f          // window half-width used only for bucketing
#define BCAP 96           // max edges per 128-px bucket
#define NT 256

__global__ __launch_bounds__(NT)
void bvr_fused_kernel(const float* __restrict__ cp,
                      const float* __restrict__ color,
                      float* __restrict__ out)
{
    __shared__ float2 s_pts[MM];        // sampled path points
    __shared__ float2 s_bk[9][BCAP];    // bucket lists: {w, xc}
    __shared__ int    s_bcnt[9];
    __shared__ float  s_btot[9];

    const int tid = threadIdx.x;
    const int y   = blockIdx.x;
    const float fy = (float)y;

    if (tid < 9) { s_bcnt[tid] = 0; s_btot[tid] = 0.0f; }

    // ---- 1. Sample Bezier path (2 points per thread) ----
    #pragma unroll
    for (int it = 0; it < 2; ++it) {
        int i = tid + it * NT;
        int s = i >> 5;
        int j = i & 31;
        float t  = (float)j / 31.0f;
        float mt = 1.0f - t;
        float b0 = mt * mt * mt;
        float b1 = 3.0f * mt * mt * t;
        float b2 = 3.0f * mt * t * t;
        float b3 = t * t * t;
        const float* p = cp + 6 * s;
        float px = b0 * p[0] + b1 * p[2] + b2 * p[4] + b3 * p[6];
        float py = b0 * p[1] + b1 * p[3] + b2 * p[5] + b3 * p[7];
        s_pts[i] = make_float2(px, py);
    }
    __syncthreads();

    // ---- 2. Compact active edges into 128-px buckets (by window start) ----
    #pragma unroll
    for (int it = 0; it < 2; ++it) {
        int e = tid + it * NT;
        float2 p0 = s_pts[e];
        float2 p1 = s_pts[(e + 1) & (MM - 1)];
        float dy = p1.y - p0.y;
        if (fabsf(dy) < 1e-6f) continue;            // coeff == 0 in reference

        float ba = p0.y - 1.2f * dy;                // |w|>1e-10 needs t in [-1.2,2.2]
        float bb = p0.y + 2.2f * dy;
        if (fy < fminf(ba, bb) || fy > fmaxf(ba, bb)) continue;

        float t  = __fdividef(fy - p0.y, dy + 1e-8f);
        float v1 = 1.0f / (1.0f + __expf(-20.0f * t));
        float v2 = 1.0f / (1.0f + __expf(20.0f * (t - 1.0f)));
        float coeff = (dy > 0.0f) ? 1.0f : -1.0f;
        float w  = coeff * v1 * v2;
        if (fabsf(w) < 1e-10f) continue;

        float xc = p0.x + t * (p1.x - p0.x);
        if (xc < -TW) continue;                     // sigma ~0 across whole row

        int xlo = (int)ceilf(xc - TW);
        xlo = max(0, min(xlo, WW));
        int bkt = min(xlo >> 7, 8);                 // 0..7 bands, 8 = right of row

        int slot = atomicAdd(&s_bcnt[bkt], 1);
        s_bk[bkt][slot] = make_float2(w, xc);
        atomicAdd(&s_btot[bkt], w);
    }
    __syncthreads();

    // ---- 3. Direct evaluation: suffix buckets (full w) + nearby buckets ----
    const int wrp = tid >> 5;                       // warp covers px [wrp*128,+128)
    const float bf = (float)(tid * 4);              // this thread's first pixel

    float wbase = 0.0f;
    #pragma unroll
    for (int j = 1; j <= 8; ++j)
        wbase += (j > wrp) ? s_btot[j] : 0.0f;      // predicated

    float wa0 = wbase, wa1 = wbase, wa2 = wbase, wa3 = wbase;

    // Edges whose transition can touch this warp's band live in buckets
    // wrp-1 and wrp. sigmoid saturates naturally -> exact, no window clamp.
    const int bb0 = (wrp > 0) ? (wrp - 1) : 0;
    for (int bb = bb0; bb <= wrp; ++bb) {
        const int cnt = s_bcnt[bb];                 // warp-uniform
        for (int s = 0; s < cnt; ++s) {
            float2 ek = s_bk[bb][s];                // broadcast LDS.64
            float hw = 0.5f * ek.x;                 // w/2
            float hu = 0.5f * (ek.y - bf);          // (xc - x0)/2
            // w * sigmoid(xc - x) = hw * tanh((xc-x)/2) + hw
            float t0, t1, t2, t3;
            asm("tanh.approx.f32 %0, %1;" : "=f"(t0) : "f"(hu));
            asm("tanh.approx.f32 %0, %1;" : "=f"(t1) : "f"(hu - 0.5f));
            asm("tanh.approx.f32 %0, %1;" : "=f"(t2) : "f"(hu - 1.0f));
            asm("tanh.approx.f32 %0, %1;" : "=f"(t3) : "f"(hu - 1.5f));
            wa0 += fmaf(hw, t0, hw);
            wa1 += fmaf(hw, t1, hw);
            wa2 += fmaf(hw, t2, hw);
            wa3 += fmaf(hw, t3, hw);
        }
    }

    // ---- 4. Alpha via tanh.approx + output ----
    const float cr = __ldg(color + 0);
    const float cg = __ldg(color + 1);
    const float cb = __ldg(color + 2);

    float wind[4] = {wa0, wa1, wa2, wa3};
    float4* orow = (float4*)out + (size_t)y * WW + tid * 4;
    #pragma unroll
    for (int q = 0; q < 4; ++q) {
        float th;                                   // sigmoid(4w)=0.5+0.5tanh(2w)
        asm("tanh.approx.f32 %0, %1;" : "=f"(th) : "f"(2.0f * wind[q]));
        float a = fmaf(0.5f, th, 0.5f);
        orow[q] = make_float4(cr, cg, cb, a);
    }
}

extern "C" void kernel_launch(void* const* d_in, const int* in_sizes, int n_in,
                              void* d_out, int out_size)
{
    const float* cp    = (const float*)d_in[0];   // (49, 2) float32
    const float* color = (const float*)d_in[1];   // (3,)   float32
    float* out = (float*)d_out;                   // (1024, 1024, 4) float32
    (void)in_sizes; (void)n_in; (void)out_size;
    bvr_fused_kernel<<<HH, NT>>>(cp, color, out);
}

// round 13
// speedup vs baseline: 1.5507x; 1.1188x over previous
#include <cuda_runtime.h>

#define HH 1024
#define WW 1024
#define MM 512            // 16 segments * 32 samples
#define TW 16.0f          // window half-width used only for bucketing
#define BCAP 96           // max edges per 128-px bucket
#define NT 256

__global__ __launch_bounds__(NT)
void bvr_fused_kernel(const float* __restrict__ cp,
                      const float* __restrict__ color,
                      float* __restrict__ out)
{
    __shared__ float2 s_pts[MM + 2];    // sampled path points (+wrap pad)
    __shared__ float2 s_bk[9][BCAP];    // bucket lists: {w, xc}
    __shared__ int    s_bcnt[9];
    __shared__ float  s_btot[9];

    const int tid = threadIdx.x;
    const int y   = blockIdx.x;
    const float fy = (float)y;

    if (tid < 9) { s_bcnt[tid] = 0; s_btot[tid] = 0.0f; }

    // ---- 1. Sample Bezier path (2 points per thread) ----
    #pragma unroll
    for (int it = 0; it < 2; ++it) {
        int i = tid + it * NT;
        int s = i >> 5;
        int j = i & 31;
        float t  = (float)j * (1.0f / 31.0f);   // j=31 -> exactly 1.0f
        float mt = 1.0f - t;
        float b0 = mt * mt * mt;
        float b1 = 3.0f * mt * mt * t;
        float b2 = 3.0f * mt * t * t;
        float b3 = t * t * t;
        const float* p = cp + 6 * s;
        float px = b0 * p[0] + b1 * p[2] + b2 * p[4] + b3 * p[6];
        float py = b0 * p[1] + b1 * p[3] + b2 * p[5] + b3 * p[7];
        float2 pt = make_float2(px, py);
        s_pts[i] = pt;
        if (i == 0) s_pts[MM] = pt;             // wrap point for edge 511
    }
    __syncthreads();

    // ---- 2. Compact edge pair (2t, 2t+1) into 128-px buckets ----
    {
        const int e0 = tid * 2;
        float4 pp = *(const float4*)&s_pts[e0];     // points e0, e0+1 (LDS.128)
        float2 p2 = s_pts[e0 + 2];                  // point e0+2 (LDS.64)
        float2 eP0[2] = { make_float2(pp.x, pp.y), make_float2(pp.z, pp.w) };
        float2 eP1[2] = { make_float2(pp.z, pp.w), p2 };

        #pragma unroll
        for (int h = 0; h < 2; ++h) {
            float2 p0 = eP0[h];
            float2 p1 = eP1[h];
            float dy = p1.y - p0.y;
            if (fabsf(dy) < 1e-6f) continue;        // coeff == 0 in reference

            float ba = p0.y - 1.2f * dy;            // |w|>1e-10 needs t in [-1.2,2.2]
            float bb = p0.y + 2.2f * dy;
            if (fy < fminf(ba, bb) || fy > fmaxf(ba, bb)) continue;

            float t = __fdividef(fy - p0.y, dy + 1e-8f);
            // v1*v2 = 1 / (1 + e^-20t + e^(20t-20) + e^-20)  (exact expansion)
            float ea = __expf(-20.0f * t);
            float eb = __expf(20.0f * (t - 1.0f));
            float denom = 1.0f + ea + eb + 2.0611537e-9f;
            if (denom > 1e10f) continue;            // |w| < 1e-10

            float coeff = (dy > 0.0f) ? 1.0f : -1.0f;
            float w  = __fdividef(coeff, denom);
            float xc = p0.x + t * (p1.x - p0.x);
            if (xc < -TW) continue;                 // sigma ~0 across whole row

            int xlo = (int)ceilf(xc - TW);
            xlo = max(0, min(xlo, WW));
            int bkt = min(xlo >> 7, 8);             // 0..7 bands, 8 = right of row

            int slot = atomicAdd(&s_bcnt[bkt], 1);
            s_bk[bkt][slot] = make_float2(w, xc);
            atomicAdd(&s_btot[bkt], w);
        }
    }
    __syncthreads();

    // ---- 3. Direct evaluation: suffix buckets (full w) + nearby buckets ----
    const int wrp = tid >> 5;                       // warp covers px [wrp*128,+128)
    const float bf = (float)(tid * 4);              // this thread's first pixel

    float wbase = 0.0f;
    #pragma unroll
    for (int j = 1; j <= 8; ++j)
        wbase += (j > wrp) ? s_btot[j] : 0.0f;      // predicated

    float wa0 = wbase, wa1 = wbase, wa2 = wbase, wa3 = wbase;

    // Edges whose transition can touch this warp's band live in buckets
    // wrp-1 and wrp. sigmoid saturates naturally -> exact, no window clamp.
    const int bb0 = (wrp > 0) ? (wrp - 1) : 0;
    for (int bb = bb0; bb <= wrp; ++bb) {
        const int cnt = s_bcnt[bb];                 // warp-uniform
        for (int s = 0; s < cnt; ++s) {
            float2 ek = s_bk[bb][s];                // broadcast LDS.64
            float hw = 0.5f * ek.x;                 // w/2
            float hu = 0.5f * (ek.y - bf);          // (xc - x0)/2
            // w * sigmoid(xc - x) = hw * tanh((xc-x)/2) + hw
            float t0, t1, t2, t3;
            asm("tanh.approx.f32 %0, %1;" : "=f"(t0) : "f"(hu));
            asm("tanh.approx.f32 %0, %1;" : "=f"(t1) : "f"(hu - 0.5f));
            asm("tanh.approx.f32 %0, %1;" : "=f"(t2) : "f"(hu - 1.0f));
            asm("tanh.approx.f32 %0, %1;" : "=f"(t3) : "f"(hu - 1.5f));
            wa0 += fmaf(hw, t0, hw);
            wa1 += fmaf(hw, t1, hw);
            wa2 += fmaf(hw, t2, hw);
            wa3 += fmaf(hw, t3, hw);
        }
    }

    // ---- 4. Alpha via tanh.approx + output ----
    const float cr = __ldg(color + 0);
    const float cg = __ldg(color + 1);
    const float cb = __ldg(color + 2);

    float wind[4] = {wa0, wa1, wa2, wa3};
    float4* orow = (float4*)out + (size_t)y * WW + tid * 4;
    #pragma unroll
    for (int q = 0; q < 4; ++q) {
        float th;                                   // sigmoid(4w)=0.5+0.5tanh(2w)
        asm("tanh.approx.f32 %0, %1;" : "=f"(th) : "f"(2.0f * wind[q]));
        float a = fmaf(0.5f, th, 0.5f);
        orow[q] = make_float4(cr, cg, cb, a);
    }
}

extern "C" void kernel_launch(void* const* d_in, const int* in_sizes, int n_in,
                              void* d_out, int out_size)
{
    const float* cp    = (const float*)d_in[0];   // (49, 2) float32
    const float* color = (const float*)d_in[1];   // (3,)   float32
    float* out = (float*)d_out;                   // (1024, 1024, 4) float32
    (void)in_sizes; (void)n_in; (void)out_size;
    bvr_fused_kernel<<<HH, NT>>>(cp, color, out);
}